// round 5
// baseline (speedup 1.0000x reference)
#include <cuda_runtime.h>
#include <cuda_bf16.h>
#include <cstdint>
#include <math.h>

// Problem constants
#define S_   2048
#define E_   1024
#define H_   16
#define DH_  64
#define KNB  64
#define E3_  (3*E_)
#define MASKV (-1e10f)

// Scratch (__device__ globals; allocation-free rule)
__device__ float g_qkv[(size_t)S_ * E3_];     // [S, 3E]  (q | k | v)
__device__ float g_attn[(size_t)S_ * E_];     // [S, E]

// ---------------------------------------------------------------------------
// bf16-split tensor-core GEMM (NT): C[M,N] = A[M,K] @ B[N,K]^T + bias[N]
// fp32 accuracy via 3-MMA bf16 split (AhBh + AhBl + AlBh).
// Tile 128x128x64, 512 threads (16 warps, 32x32 warp tiles),
// double-buffered SW128-swizzled smem, mma.sync.m16n8k16 + ldmatrix.
// ---------------------------------------------------------------------------
#define TILEB  16384                 // 128 rows x 128 B (64 bf16)
#define STAGEB (4 * TILEB)           // Ah, Al, Bh, Bl
#define GSMEM  (2 * STAGEB)          // 131072 B

__device__ __forceinline__ uint32_t smem_u32(const void* p) {
    uint32_t a;
    asm("{ .reg .u64 t; cvta.to.shared.u64 t, %1; cvt.u32.u64 %0, t; }" : "=r"(a) : "l"(p));
    return a;
}
__device__ __forceinline__ uint32_t sw128(uint32_t off) {
    return off ^ ((off >> 3) & 0x70);
}

#define LDSM4(r, a) \
    asm volatile("ldmatrix.sync.aligned.m8n8.x4.shared.b16 {%0,%1,%2,%3}, [%4];" \
        : "=r"((r)[0]), "=r"((r)[1]), "=r"((r)[2]), "=r"((r)[3]) : "r"(a))

__device__ __forceinline__ void mma16816(float* d, const uint32_t* a, const uint32_t* b) {
    asm volatile("mma.sync.aligned.m16n8k16.row.col.f32.bf16.bf16.f32 "
        "{%0,%1,%2,%3}, {%4,%5,%6,%7}, {%8,%9}, {%0,%1,%2,%3};"
        : "+f"(d[0]), "+f"(d[1]), "+f"(d[2]), "+f"(d[3])
        : "r"(a[0]), "r"(a[1]), "r"(a[2]), "r"(a[3]), "r"(b[0]), "r"(b[1]));
}

__device__ __forceinline__ void split4(float4 v, uint2& h, uint2& l) {
    __nv_bfloat162 h0 = __float22bfloat162_rn(make_float2(v.x, v.y));
    __nv_bfloat162 h1 = __float22bfloat162_rn(make_float2(v.z, v.w));
    float2 f0 = __bfloat1622float2(h0);
    float2 f1 = __bfloat1622float2(h1);
    __nv_bfloat162 l0 = __float22bfloat162_rn(make_float2(v.x - f0.x, v.y - f0.y));
    __nv_bfloat162 l1 = __float22bfloat162_rn(make_float2(v.z - f1.x, v.w - f1.y));
    h.x = *(uint32_t*)&h0; h.y = *(uint32_t*)&h1;
    l.x = *(uint32_t*)&l0; l.y = *(uint32_t*)&l1;
}

__global__ __launch_bounds__(512)
void bf16_gemm_nt_bias(const float* __restrict__ A, const float* __restrict__ B,
                       const float* __restrict__ bias, float* __restrict__ C,
                       int M, int N, int K)
{
    extern __shared__ char sm[];
    const uint32_t sbase = smem_u32(sm);

    const int tid  = threadIdx.x;
    const int lane = tid & 31;
    const int wid  = tid >> 5;
    const int wm   = (wid >> 2) * 32;   // warp m offset within 128
    const int wn   = (wid & 3) * 32;    // warp n offset within 128
    const int m0   = blockIdx.y * 128;
    const int n0   = blockIdx.x * 128;

    float d[2][4][4];
#pragma unroll
    for (int i = 0; i < 2; i++)
#pragma unroll
        for (int j = 0; j < 4; j++)
#pragma unroll
            for (int q = 0; q < 4; q++) d[i][j][q] = 0.f;

    // staging coords: 512 threads, 8 float4 each (4 A + 4 B)
    const int srow = tid >> 4;          // 0..31 (+32*i)
    const int sq   = tid & 15;          // 16B chunk within 64-float row

    float4 ra[4], rb[4];

    auto gload = [&](int k0) {
#pragma unroll
        for (int i = 0; i < 4; i++) {
            int row = srow + i * 32;
            ra[i] = *(const float4*)(A + (size_t)(m0 + row) * K + k0 + sq * 4);
            rb[i] = *(const float4*)(B + (size_t)(n0 + row) * K + k0 + sq * 4);
        }
    };
    auto sstore = [&](int s) {
        char* base = sm + s * STAGEB;
#pragma unroll
        for (int i = 0; i < 4; i++) {
            int row = srow + i * 32;
            uint32_t off = sw128(row * 128 + sq * 8);
            uint2 h, l;
            split4(ra[i], h, l);
            *(uint2*)(base + off)             = h;
            *(uint2*)(base + TILEB + off)     = l;
            split4(rb[i], h, l);
            *(uint2*)(base + 2 * TILEB + off) = h;
            *(uint2*)(base + 3 * TILEB + off) = l;
        }
    };

    auto compute = [&](int s) {
        const uint32_t sb = sbase + s * STAGEB;
#pragma unroll
        for (int ks = 0; ks < 4; ks++) {
            const uint32_t colb = ks * 32 + ((lane >> 4) << 4);

            uint32_t bh[4][2], bl[4][2];
#pragma unroll
            for (int ng = 0; ng < 2; ng++) {
                uint32_t off = sw128((wn + ng * 16 + (lane & 15)) * 128 + colb);
                uint32_t r[4];
                LDSM4(r, sb + 2 * TILEB + off);
                bh[ng * 2 + 0][0] = r[0]; bh[ng * 2 + 0][1] = r[2];
                bh[ng * 2 + 1][0] = r[1]; bh[ng * 2 + 1][1] = r[3];
                LDSM4(r, sb + 3 * TILEB + off);
                bl[ng * 2 + 0][0] = r[0]; bl[ng * 2 + 0][1] = r[2];
                bl[ng * 2 + 1][0] = r[1]; bl[ng * 2 + 1][1] = r[3];
            }

#pragma unroll
            for (int mt = 0; mt < 2; mt++) {
                uint32_t off = sw128((wm + mt * 16 + (lane & 15)) * 128 + colb);
                uint32_t ah[4], al[4];
                LDSM4(ah, sb + off);
                LDSM4(al, sb + TILEB + off);
#pragma unroll
                for (int nt = 0; nt < 4; nt++) {
                    mma16816(d[mt][nt], ah, bh[nt]);
                    mma16816(d[mt][nt], ah, bl[nt]);
                    mma16816(d[mt][nt], al, bh[nt]);
                }
            }
        }
    };

    gload(0);
    sstore(0);
    __syncthreads();

    const int NC = K / 64;
    for (int c = 0; c < NC; c++) {
        const int s = c & 1;
        if (c + 1 < NC) gload((c + 1) * 64);
        compute(s);
        if (c + 1 < NC) sstore(s ^ 1);
        __syncthreads();
    }

    // epilogue
#pragma unroll
    for (int mt = 0; mt < 2; mt++) {
        const int r0 = m0 + wm + mt * 16 + (lane >> 2);
#pragma unroll
        for (int nt = 0; nt < 4; nt++) {
            const int c0 = n0 + wn + nt * 8 + (lane & 3) * 2;
            const float b0 = bias[c0], b1 = bias[c0 + 1];
            float2 o;
            o.x = d[mt][nt][0] + b0;
            o.y = d[mt][nt][1] + b1;
            *(float2*)(C + (size_t)r0 * N + c0) = o;
            o.x = d[mt][nt][2] + b0;
            o.y = d[mt][nt][3] + b1;
            *(float2*)(C + (size_t)(r0 + 8) * N + c0) = o;
        }
    }
}

// ---------------------------------------------------------------------------
// Banded scores + softmax + attn@V — float4 smem paths, overlapped phases
// ---------------------------------------------------------------------------
#define TI    8
#define NUMAX 144
#define KVST  80                      // floats per KV row (float4-conflict-free)
#define NT    256
// dynamic smem layout (floats):
//   KVs [NUMAX*KVST]  = 11520
//   Qs  [TI*KVST]     = 640
//   Sc  [TI*NUMAX]    = 1152  (raw scores)
//   Pr  [TI*NUMAX]    = 1152  (probabilities)
#define SC_SMEM ((NUMAX*KVST + TI*KVST + 2*TI*NUMAX) * 4)

__global__ __launch_bounds__(NT)
void scores_attn_kernel(const float* __restrict__ qkv,
                        float* __restrict__ scores_out,
                        float* __restrict__ attn_out)
{
    extern __shared__ float smf[];
    float* KVs = smf;
    float* Qs  = KVs + NUMAX * KVST;
    float* Sc  = Qs + TI * KVST;
    float* Pr  = Sc + TI * NUMAX;

    const int h  = blockIdx.y;
    const int i0 = blockIdx.x * TI;
    const int t  = threadIdx.x;

    const int j0 = max(0, i0 - KNB);
    const int j1 = min(S_ - 1, i0 + TI - 1 + KNB);
    const int NU = j1 - j0 + 1;             // <= 136

    const int hoff = h * DH_;

    // load Q tile [TI x 64] (float4)
    for (int idx = t; idx < TI * 16; idx += NT) {
        int r = idx >> 4, dq = idx & 15;
        *(float4*)(Qs + r * KVST + dq * 4) =
            *(const float4*)(qkv + (size_t)(i0 + r) * E3_ + hoff + dq * 4);
    }
    // load K band [NU x 64] (float4)
    for (int idx = t; idx < NU * 16; idx += NT) {
        int u = idx >> 4, dq = idx & 15;
        *(float4*)(KVs + u * KVST + dq * 4) =
            *(const float4*)(qkv + (size_t)(j0 + u) * E3_ + E_ + hoff + dq * 4);
    }
    __syncthreads();

    // scores: thread t owns key column u=t, float4 dot over d
    if (t < NU) {
        const int j = j0 + t;
        const float4* kv4 = (const float4*)(KVs + t * KVST);
#pragma unroll
        for (int r = 0; r < TI; r++) {
            const int i = i0 + r;
            float val;
            if (abs(i - j) <= KNB) {
                const float4* q4 = (const float4*)(Qs + r * KVST);
                float s = 0.f;
#pragma unroll
                for (int dq = 0; dq < 16; dq++) {
                    float4 a = q4[dq], b = kv4[dq];
                    s = fmaf(a.x, b.x, s);
                    s = fmaf(a.y, b.y, s);
                    s = fmaf(a.z, b.z, s);
                    s = fmaf(a.w, b.w, s);
                }
                val = s * 0.125f;
            } else {
                val = -INFINITY;
            }
            Sc[r * NUMAX + t] = val;
        }
    }
    __syncthreads();

    // --- overlapped region: softmax (Sc -> Pr), V-band load, scores stores ---

    // softmax per row: warp w handles row w (reads Sc, writes Pr)
    const int w = t >> 5, lane = t & 31;
    {
        float m = -INFINITY;
        for (int u = lane; u < NU; u += 32)
            m = fmaxf(m, Sc[w * NUMAX + u]);
#pragma unroll
        for (int o = 16; o; o >>= 1)
            m = fmaxf(m, __shfl_xor_sync(0xFFFFFFFFu, m, o));
        float ssum = 0.f;
        for (int u = lane; u < NU; u += 32) {
            float e = expf(Sc[w * NUMAX + u] - m);
            Pr[w * NUMAX + u] = e;
            ssum += e;
        }
#pragma unroll
        for (int o = 16; o; o >>= 1)
            ssum += __shfl_xor_sync(0xFFFFFFFFu, ssum, o);
        float inv = 1.f / ssum;
        for (int u = lane; u < NU; u += 32)
            Pr[w * NUMAX + u] *= inv;
    }

    // V band load (overwrites K band; K no longer needed)
    for (int idx = t; idx < NU * 16; idx += NT) {
        int u = idx >> 4, dq = idx & 15;
        *(float4*)(KVs + u * KVST + dq * 4) =
            *(const float4*)(qkv + (size_t)(j0 + u) * E3_ + 2 * E_ + hoff + dq * 4);
    }

    // write full masked scores rows (reads Sc only)
#pragma unroll
    for (int r = 0; r < TI; r++) {
        const int i = i0 + r;
        const int lo = i - KNB, hi = i + KNB;
        float* rowp = scores_out + ((size_t)h * S_ + i) * S_;
#pragma unroll
        for (int it = 0; it < S_ / (NT * 4); it++) {
            const int j = (it * NT + t) * 4;
            float4 v;
            v.x = (j + 0 >= lo && j + 0 <= hi) ? Sc[r * NUMAX + (j + 0 - j0)] : MASKV;
            v.y = (j + 1 >= lo && j + 1 <= hi) ? Sc[r * NUMAX + (j + 1 - j0)] : MASKV;
            v.z = (j + 2 >= lo && j + 2 <= hi) ? Sc[r * NUMAX + (j + 2 - j0)] : MASKV;
            v.w = (j + 3 >= lo && j + 3 <= hi) ? Sc[r * NUMAX + (j + 3 - j0)] : MASKV;
            *(float4*)(rowp + j) = v;
        }
    }
    __syncthreads();

    // attn @ V : threads 0..127, thread owns (row r, 4 d-columns)
    if (t < 128) {
        const int r  = t >> 4;
        const int dg = t & 15;
        const float4* kv4 = (const float4*)(KVs) + dg;
        const float*  pr  = Pr + r * NUMAX;
        float4 acc = make_float4(0.f, 0.f, 0.f, 0.f);
        for (int u = 0; u < NU; u++) {
            const float p = pr[u];
            const float4 v = kv4[u * (KVST / 4)];
            acc.x = fmaf(p, v.x, acc.x);
            acc.y = fmaf(p, v.y, acc.y);
            acc.z = fmaf(p, v.z, acc.z);
            acc.w = fmaf(p, v.w, acc.w);
        }
        *(float4*)(attn_out + (size_t)(i0 + r) * E_ + hoff + dg * 4) = acc;
    }
}

// ---------------------------------------------------------------------------
// launch
// ---------------------------------------------------------------------------
extern "C" void kernel_launch(void* const* d_in, const int* in_sizes, int n_in,
                              void* d_out, int out_size)
{
    const float* x     = (const float*)d_in[0];   // [S, E]
    const float* W_qkv = (const float*)d_in[1];   // [3E, E]
    const float* b_qkv = (const float*)d_in[2];   // [3E]
    const float* W_out = (const float*)d_in[3];   // [E, E]
    const float* b_out = (const float*)d_in[4];   // [E]

    float* out_ptr    = (float*)d_out;                 // [S, E]
    float* scores_ptr = out_ptr + (size_t)S_ * E_;     // [H, S, S]

    float *qkv_p, *attn_p;
    cudaGetSymbolAddress((void**)&qkv_p,  g_qkv);
    cudaGetSymbolAddress((void**)&attn_p, g_attn);

    cudaFuncSetAttribute(bf16_gemm_nt_bias,
                         cudaFuncAttributeMaxDynamicSharedMemorySize, GSMEM);
    cudaFuncSetAttribute(scores_attn_kernel,
                         cudaFuncAttributeMaxDynamicSharedMemorySize, SC_SMEM);

    // 1) QKV projection
    {
        dim3 grid(E3_ / 128, S_ / 128);
        bf16_gemm_nt_bias<<<grid, 512, GSMEM>>>(x, W_qkv, b_qkv, qkv_p,
                                                S_, E3_, E_);
    }

    // 2) banded scores + softmax + attn@V
    {
        dim3 grid(S_ / TI, H_);
        scores_attn_kernel<<<grid, NT, SC_SMEM>>>(qkv_p, scores_ptr, attn_p);
    }

    // 3) output projection
    {
        dim3 grid(E_ / 128, S_ / 128);
        bf16_gemm_nt_bias<<<grid, 512, GSMEM>>>(attn_p, W_out, b_out, out_ptr,
                                                S_, E_, E_);
    }
}

// round 6
// speedup vs baseline: 1.2063x; 1.2063x over previous
#include <cuda_runtime.h>
#include <cuda_bf16.h>
#include <cstdint>
#include <math.h>

// Problem constants
#define S_   2048
#define E_   1024
#define H_   16
#define DH_  64
#define KNB  64
#define E3_  (3*E_)
#define MASKV (-1e10f)

// Scratch (__device__ globals; allocation-free rule)
__device__ float g_qkv[(size_t)S_ * E3_];            // [S, 3E]
__device__ __nv_bfloat16 g_xh[(size_t)S_ * E_];      // x hi/lo
__device__ __nv_bfloat16 g_xl[(size_t)S_ * E_];
__device__ __nv_bfloat16 g_wqh[(size_t)E3_ * E_];    // W_qkv hi/lo
__device__ __nv_bfloat16 g_wql[(size_t)E3_ * E_];
__device__ __nv_bfloat16 g_woh[(size_t)E_ * E_];     // W_out hi/lo
__device__ __nv_bfloat16 g_wol[(size_t)E_ * E_];
__device__ __nv_bfloat16 g_ah[(size_t)S_ * E_];      // attn hi/lo
__device__ __nv_bfloat16 g_al[(size_t)S_ * E_];

// ---------------------------------------------------------------------------
// helpers
// ---------------------------------------------------------------------------
__device__ __forceinline__ uint32_t smem_u32(const void* p) {
    uint32_t a;
    asm("{ .reg .u64 t; cvta.to.shared.u64 t, %1; cvt.u32.u64 %0, t; }" : "=r"(a) : "l"(p));
    return a;
}
__device__ __forceinline__ uint32_t sw128(uint32_t off) {
    return off ^ ((off >> 3) & 0x70);
}
#define LDSM4(r, a) \
    asm volatile("ldmatrix.sync.aligned.m8n8.x4.shared.b16 {%0,%1,%2,%3}, [%4];" \
        : "=r"((r)[0]), "=r"((r)[1]), "=r"((r)[2]), "=r"((r)[3]) : "r"(a))

__device__ __forceinline__ void mma16816(float* d, const uint32_t* a, const uint32_t* b) {
    asm volatile("mma.sync.aligned.m16n8k16.row.col.f32.bf16.bf16.f32 "
        "{%0,%1,%2,%3}, {%4,%5,%6,%7}, {%8,%9}, {%0,%1,%2,%3};"
        : "+f"(d[0]), "+f"(d[1]), "+f"(d[2]), "+f"(d[3])
        : "r"(a[0]), "r"(a[1]), "r"(a[2]), "r"(a[3]), "r"(b[0]), "r"(b[1]));
}
#define CP_ASYNC16(dst, src) \
    asm volatile("cp.async.cg.shared.global [%0], [%1], 16;" :: "r"(dst), "l"(src))
#define CP_COMMIT() asm volatile("cp.async.commit_group;" ::: "memory")
#define CP_WAIT1()  asm volatile("cp.async.wait_group 1;" ::: "memory")
#define CP_WAIT0()  asm volatile("cp.async.wait_group 0;" ::: "memory")

// ---------------------------------------------------------------------------
// split kernel: fp32 -> bf16 hi + bf16 lo
// ---------------------------------------------------------------------------
__global__ __launch_bounds__(256)
void split_bf16(const float4* __restrict__ in, uint2* __restrict__ hi,
                uint2* __restrict__ lo, int n4)
{
    int i = blockIdx.x * 256 + threadIdx.x;
    if (i >= n4) return;
    float4 v = in[i];
    __nv_bfloat162 h0 = __float22bfloat162_rn(make_float2(v.x, v.y));
    __nv_bfloat162 h1 = __float22bfloat162_rn(make_float2(v.z, v.w));
    float2 f0 = __bfloat1622float2(h0);
    float2 f1 = __bfloat1622float2(h1);
    __nv_bfloat162 l0 = __float22bfloat162_rn(make_float2(v.x - f0.x, v.y - f0.y));
    __nv_bfloat162 l1 = __float22bfloat162_rn(make_float2(v.z - f1.x, v.w - f1.y));
    uint2 h, l;
    h.x = *(uint32_t*)&h0; h.y = *(uint32_t*)&h1;
    l.x = *(uint32_t*)&l0; l.y = *(uint32_t*)&l1;
    hi[i] = h;
    lo[i] = l;
}

// ---------------------------------------------------------------------------
// bf16-split tensor GEMM (NT): C[M,N] = A[M,K] @ B[N,K]^T + bias[N]
// A,B pre-split bf16 (hi,lo). 3-MMA scheme. Tile 128x128x64, 512 threads.
// cp.async double-buffered SW128 smem.
// ---------------------------------------------------------------------------
#define TILEB  16384                 // 128 rows x 128 B (64 bf16)
#define STAGEB (4 * TILEB)
#define GSMEM  (2 * STAGEB)          // 131072 B

__global__ __launch_bounds__(512)
void bf16s_gemm_nt_bias(const __nv_bfloat16* __restrict__ Ah,
                        const __nv_bfloat16* __restrict__ Al,
                        const __nv_bfloat16* __restrict__ Bh,
                        const __nv_bfloat16* __restrict__ Bl,
                        const float* __restrict__ bias, float* __restrict__ C,
                        int M, int N, int K)
{
    extern __shared__ char sm[];
    const uint32_t sbase = smem_u32(sm);

    const int tid  = threadIdx.x;
    const int lane = tid & 31;
    const int wid  = tid >> 5;
    const int wm   = (wid >> 2) * 32;
    const int wn   = (wid & 3) * 32;
    const int m0   = blockIdx.y * 128;
    const int n0   = blockIdx.x * 128;

    const __nv_bfloat16* tbase[4] = {
        Ah + (size_t)m0 * K, Al + (size_t)m0 * K,
        Bh + (size_t)n0 * K, Bl + (size_t)n0 * K
    };

    float d[2][4][4];
#pragma unroll
    for (int i = 0; i < 2; i++)
#pragma unroll
        for (int j = 0; j < 4; j++)
#pragma unroll
            for (int q = 0; q < 4; q++) d[i][j][q] = 0.f;

    // stage copy: 4 tiles x 1024 16B-chunks = 4096 chunks; 8 per thread
    auto issue = [&](int c) {
        const int s = c & 1;
        const int k0 = c * 64;
        const uint32_t sb = sbase + s * STAGEB;
#pragma unroll
        for (int i = 0; i < 8; i++) {
            const int tile = i >> 1;                 // compile-time
            const int idx  = i * 512 + tid;
            const int row  = (idx >> 3) & 127;
            const int q    = idx & 7;
            const __nv_bfloat16* src = tbase[tile] + (size_t)row * K + k0 + q * 8;
            const uint32_t dst = sb + tile * TILEB + sw128(row * 128 + q * 16);
            CP_ASYNC16(dst, src);
        }
        CP_COMMIT();
    };

    auto compute = [&](int s) {
        const uint32_t sb = sbase + s * STAGEB;
#pragma unroll
        for (int ks = 0; ks < 4; ks++) {
            const uint32_t colb = ks * 32 + ((lane >> 4) << 4);

            uint32_t bh[4][2], bl[4][2];
#pragma unroll
            for (int ng = 0; ng < 2; ng++) {
                uint32_t off = sw128((wn + ng * 16 + (lane & 15)) * 128 + colb);
                uint32_t r[4];
                LDSM4(r, sb + 2 * TILEB + off);
                bh[ng * 2 + 0][0] = r[0]; bh[ng * 2 + 0][1] = r[2];
                bh[ng * 2 + 1][0] = r[1]; bh[ng * 2 + 1][1] = r[3];
                LDSM4(r, sb + 3 * TILEB + off);
                bl[ng * 2 + 0][0] = r[0]; bl[ng * 2 + 0][1] = r[2];
                bl[ng * 2 + 1][0] = r[1]; bl[ng * 2 + 1][1] = r[3];
            }

#pragma unroll
            for (int mt = 0; mt < 2; mt++) {
                uint32_t off = sw128((wm + mt * 16 + (lane & 15)) * 128 + colb);
                uint32_t ah[4], al[4];
                LDSM4(ah, sb + off);
                LDSM4(al, sb + TILEB + off);
#pragma unroll
                for (int nt = 0; nt < 4; nt++) {
                    mma16816(d[mt][nt], ah, bh[nt]);
                    mma16816(d[mt][nt], ah, bl[nt]);
                    mma16816(d[mt][nt], al, bh[nt]);
                }
            }
        }
    };

    const int NC = K / 64;
    issue(0);
    for (int c = 0; c < NC; c++) {
        if (c + 1 < NC) {
            issue(c + 1);
            CP_WAIT1();
        } else {
            CP_WAIT0();
        }
        __syncthreads();
        compute(c & 1);
        __syncthreads();
    }

    // epilogue
#pragma unroll
    for (int mt = 0; mt < 2; mt++) {
        const int r0 = m0 + wm + mt * 16 + (lane >> 2);
#pragma unroll
        for (int nt = 0; nt < 4; nt++) {
            const int c0 = n0 + wn + nt * 8 + (lane & 3) * 2;
            const float b0 = bias[c0], b1 = bias[c0 + 1];
            float2 o;
            o.x = d[mt][nt][0] + b0;
            o.y = d[mt][nt][1] + b1;
            *(float2*)(C + (size_t)r0 * N + c0) = o;
            o.x = d[mt][nt][2] + b0;
            o.y = d[mt][nt][3] + b1;
            *(float2*)(C + (size_t)(r0 + 8) * N + c0) = o;
        }
    }
}

// ---------------------------------------------------------------------------
// Banded scores + softmax + attn@V  (R4 structure: 44.3KB smem, 5 CTAs/SM)
// V-load overlapped with scores stores; explicit sync before in-place softmax.
// Emits attn as bf16 hi/lo for the out-proj GEMM.
// ---------------------------------------------------------------------------
#define TI    8
#define NUMAX 144
#define NT    256

__global__ __launch_bounds__(NT)
void scores_attn_kernel(const float* __restrict__ qkv,
                        float* __restrict__ scores_out,
                        __nv_bfloat16* __restrict__ attn_hi,
                        __nv_bfloat16* __restrict__ attn_lo)
{
    __shared__ float KVs[NUMAX * 65];
    __shared__ float Qs[TI * 65];
    __shared__ float Sc[TI * NUMAX];

    const int h  = blockIdx.y;
    const int i0 = blockIdx.x * TI;
    const int t  = threadIdx.x;

    const int j0 = max(0, i0 - KNB);
    const int j1 = min(S_ - 1, i0 + TI - 1 + KNB);
    const int NU = j1 - j0 + 1;             // <= 136

    const int hoff = h * DH_;

    for (int idx = t; idx < TI * DH_; idx += NT) {
        int r = idx >> 6, dd = idx & 63;
        Qs[r * 65 + dd] = qkv[(size_t)(i0 + r) * E3_ + hoff + dd];
    }
    for (int idx = t; idx < NU * DH_; idx += NT) {
        int u = idx >> 6, dd = idx & 63;
        KVs[u * 65 + dd] = qkv[(size_t)(j0 + u) * E3_ + E_ + hoff + dd];
    }
    __syncthreads();

    // scores: thread t owns key column u=t
    if (t < NU) {
        const int j = j0 + t;
#pragma unroll
        for (int r = 0; r < TI; r++) {
            const int i = i0 + r;
            float val;
            if (abs(i - j) <= KNB) {
                float s = 0.f;
#pragma unroll
                for (int dd = 0; dd < DH_; dd++)
                    s = fmaf(Qs[r * 65 + dd], KVs[t * 65 + dd], s);
                val = s * 0.125f;
            } else {
                val = -INFINITY;
            }
            Sc[r * NUMAX + t] = val;
        }
    }
    __syncthreads();

    // K no longer needed -> V band load overlaps the big scores stores.
    for (int idx = t; idx < NU * DH_; idx += NT) {
        int u = idx >> 6, dd = idx & 63;
        KVs[u * 65 + dd] = qkv[(size_t)(j0 + u) * E3_ + 2 * E_ + hoff + dd];
    }

    // write full masked scores rows (reads Sc), float4
#pragma unroll
    for (int r = 0; r < TI; r++) {
        const int i = i0 + r;
        const int lo = i - KNB, hi = i + KNB;
        float* rowp = scores_out + ((size_t)h * S_ + i) * S_;
#pragma unroll
        for (int it = 0; it < S_ / (NT * 4); it++) {
            const int j = (it * NT + t) * 4;
            float4 v;
            v.x = (j + 0 >= lo && j + 0 <= hi) ? Sc[r * NUMAX + (j + 0 - j0)] : MASKV;
            v.y = (j + 1 >= lo && j + 1 <= hi) ? Sc[r * NUMAX + (j + 1 - j0)] : MASKV;
            v.z = (j + 2 >= lo && j + 2 <= hi) ? Sc[r * NUMAX + (j + 2 - j0)] : MASKV;
            v.w = (j + 3 >= lo && j + 3 <= hi) ? Sc[r * NUMAX + (j + 3 - j0)] : MASKV;
            *(float4*)(rowp + j) = v;
        }
    }
    __syncthreads();   // all Sc reads done before in-place softmax

    // softmax in place (warp w -> row w)
    const int w = t >> 5, lane = t & 31;
    {
        float m = -INFINITY;
        for (int u = lane; u < NU; u += 32)
            m = fmaxf(m, Sc[w * NUMAX + u]);
#pragma unroll
        for (int o = 16; o; o >>= 1)
            m = fmaxf(m, __shfl_xor_sync(0xFFFFFFFFu, m, o));
        float ssum = 0.f;
        for (int u = lane; u < NU; u += 32) {
            float e = expf(Sc[w * NUMAX + u] - m);
            Sc[w * NUMAX + u] = e;
            ssum += e;
        }
#pragma unroll
        for (int o = 16; o; o >>= 1)
            ssum += __shfl_xor_sync(0xFFFFFFFFu, ssum, o);
        float inv = 1.f / ssum;
        for (int u = lane; u < NU; u += 32)
            Sc[w * NUMAX + u] *= inv;
    }
    __syncthreads();

    // attn @ V -> bf16 hi/lo
    {
        const int dd = t & 63;
        const int rr = t >> 6;
#pragma unroll
        for (int s = 0; s < 2; s++) {
            const int r = rr + s * 4;
            float acc = 0.f;
            for (int u = 0; u < NU; u++)
                acc = fmaf(Sc[r * NUMAX + u], KVs[u * 65 + dd], acc);
            __nv_bfloat16 hb = __float2bfloat16(acc);
            __nv_bfloat16 lb = __float2bfloat16(acc - __bfloat162float(hb));
            const size_t idx = (size_t)(i0 + r) * E_ + hoff + dd;
            attn_hi[idx] = hb;
            attn_lo[idx] = lb;
        }
    }
}

// ---------------------------------------------------------------------------
// launch
// ---------------------------------------------------------------------------
extern "C" void kernel_launch(void* const* d_in, const int* in_sizes, int n_in,
                              void* d_out, int out_size)
{
    const float* x     = (const float*)d_in[0];
    const float* W_qkv = (const float*)d_in[1];
    const float* b_qkv = (const float*)d_in[2];
    const float* W_out = (const float*)d_in[3];
    const float* b_out = (const float*)d_in[4];

    float* out_ptr    = (float*)d_out;
    float* scores_ptr = out_ptr + (size_t)S_ * E_;

    float* qkv_p;
    __nv_bfloat16 *xh, *xl, *wqh, *wql, *woh, *wol, *ah, *al;
    cudaGetSymbolAddress((void**)&qkv_p, g_qkv);
    cudaGetSymbolAddress((void**)&xh,  g_xh);
    cudaGetSymbolAddress((void**)&xl,  g_xl);
    cudaGetSymbolAddress((void**)&wqh, g_wqh);
    cudaGetSymbolAddress((void**)&wql, g_wql);
    cudaGetSymbolAddress((void**)&woh, g_woh);
    cudaGetSymbolAddress((void**)&wol, g_wol);
    cudaGetSymbolAddress((void**)&ah,  g_ah);
    cudaGetSymbolAddress((void**)&al,  g_al);

    cudaFuncSetAttribute(bf16s_gemm_nt_bias,
                         cudaFuncAttributeMaxDynamicSharedMemorySize, GSMEM);

    // splits (independent)
    {
        int n4 = (S_ * E_) / 4;
        split_bf16<<<(n4 + 255) / 256, 256>>>((const float4*)x, (uint2*)xh, (uint2*)xl, n4);
    }
    {
        int n4 = (E3_ * E_) / 4;
        split_bf16<<<(n4 + 255) / 256, 256>>>((const float4*)W_qkv, (uint2*)wqh, (uint2*)wql, n4);
    }
    {
        int n4 = (E_ * E_) / 4;
        split_bf16<<<(n4 + 255) / 256, 256>>>((const float4*)W_out, (uint2*)woh, (uint2*)wol, n4);
    }

    // 1) QKV projection
    {
        dim3 grid(E3_ / 128, S_ / 128);
        bf16s_gemm_nt_bias<<<grid, 512, GSMEM>>>(xh, xl, wqh, wql, b_qkv, qkv_p,
                                                 S_, E3_, E_);
    }

    // 2) banded scores + softmax + attn@V (emits bf16 hi/lo attn)
    {
        dim3 grid(S_ / TI, H_);
        scores_attn_kernel<<<grid, NT>>>(qkv_p, scores_ptr, ah, al);
    }

    // 3) output projection
    {
        dim3 grid(E_ / 128, S_ / 128);
        bf16s_gemm_nt_bias<<<grid, 512, GSMEM>>>(ah, al, woh, wol, b_out, out_ptr,
                                                 S_, E_, E_);
    }
}

// round 7
// speedup vs baseline: 1.3693x; 1.1351x over previous
#include <cuda_runtime.h>
#include <cuda_bf16.h>
#include <cstdint>
#include <math.h>

// Problem constants
#define S_   2048
#define E_   1024
#define H_   16
#define DH_  64
#define KNB  64
#define E3_  (3*E_)
#define MASKV (-1e10f)

// Scratch (__device__ globals)
__device__ float g_qkv[(size_t)S_ * E3_];
__device__ __nv_bfloat16 g_xh[(size_t)S_ * E_];
__device__ __nv_bfloat16 g_xl[(size_t)S_ * E_];
__device__ __nv_bfloat16 g_wqh[(size_t)E3_ * E_];
__device__ __nv_bfloat16 g_wql[(size_t)E3_ * E_];
__device__ __nv_bfloat16 g_woh[(size_t)E_ * E_];
__device__ __nv_bfloat16 g_wol[(size_t)E_ * E_];
__device__ __nv_bfloat16 g_ah[(size_t)S_ * E_];
__device__ __nv_bfloat16 g_al[(size_t)S_ * E_];

// ---------------------------------------------------------------------------
// helpers
// ---------------------------------------------------------------------------
__device__ __forceinline__ uint32_t smem_u32(const void* p) {
    uint32_t a;
    asm("{ .reg .u64 t; cvta.to.shared.u64 t, %1; cvt.u32.u64 %0, t; }" : "=r"(a) : "l"(p));
    return a;
}
__device__ __forceinline__ uint32_t sw128(uint32_t off) {
    return off ^ ((off >> 3) & 0x70);
}
#define LDSM4(r, a) \
    asm volatile("ldmatrix.sync.aligned.m8n8.x4.shared.b16 {%0,%1,%2,%3}, [%4];" \
        : "=r"((r)[0]), "=r"((r)[1]), "=r"((r)[2]), "=r"((r)[3]) : "r"(a))

__device__ __forceinline__ void mma16816(float* d, const uint32_t* a, const uint32_t* b) {
    asm volatile("mma.sync.aligned.m16n8k16.row.col.f32.bf16.bf16.f32 "
        "{%0,%1,%2,%3}, {%4,%5,%6,%7}, {%8,%9}, {%0,%1,%2,%3};"
        : "+f"(d[0]), "+f"(d[1]), "+f"(d[2]), "+f"(d[3])
        : "r"(a[0]), "r"(a[1]), "r"(a[2]), "r"(a[3]), "r"(b[0]), "r"(b[1]));
}
#define CP_ASYNC16(dst, src) \
    asm volatile("cp.async.cg.shared.global [%0], [%1], 16;" :: "r"(dst), "l"(src))
#define CP_COMMIT() asm volatile("cp.async.commit_group;" ::: "memory")
#define CP_WAIT1()  asm volatile("cp.async.wait_group 1;" ::: "memory")
#define CP_WAIT0()  asm volatile("cp.async.wait_group 0;" ::: "memory")

// ---------------------------------------------------------------------------
// split kernel: fp32 -> bf16 hi + bf16 lo
// ---------------------------------------------------------------------------
__global__ __launch_bounds__(256)
void split_bf16(const float4* __restrict__ in, uint2* __restrict__ hi,
                uint2* __restrict__ lo, int n4)
{
    int i = blockIdx.x * 256 + threadIdx.x;
    if (i >= n4) return;
    float4 v = in[i];
    __nv_bfloat162 h0 = __float22bfloat162_rn(make_float2(v.x, v.y));
    __nv_bfloat162 h1 = __float22bfloat162_rn(make_float2(v.z, v.w));
    float2 f0 = __bfloat1622float2(h0);
    float2 f1 = __bfloat1622float2(h1);
    __nv_bfloat162 l0 = __float22bfloat162_rn(make_float2(v.x - f0.x, v.y - f0.y));
    __nv_bfloat162 l1 = __float22bfloat162_rn(make_float2(v.z - f1.x, v.w - f1.y));
    uint2 h, l;
    h.x = *(uint32_t*)&h0; h.y = *(uint32_t*)&h1;
    l.x = *(uint32_t*)&l0; l.y = *(uint32_t*)&l1;
    hi[i] = h;
    lo[i] = l;
}

// ---------------------------------------------------------------------------
// bf16-split tensor GEMM (NT): C[M,N] = A[M,K] @ B[N,K]^T + bias[N]
// Tile 128x64x64, 256 threads (8 warps, 32x32 warp tiles), 2 CTAs/SM.
// cp.async double-buffered SW128 smem: stage = Ah(16K) Al(16K) Bh(8K) Bl(8K).
// ---------------------------------------------------------------------------
#define ATILEB 16384
#define BTILEB 8192
#define STAGEB (2 * ATILEB + 2 * BTILEB)     // 49152
#define GSMEM  (2 * STAGEB)                  // 98304

__global__ __launch_bounds__(256, 2)
void bf16s_gemm_nt_bias(const __nv_bfloat16* __restrict__ Ah,
                        const __nv_bfloat16* __restrict__ Al,
                        const __nv_bfloat16* __restrict__ Bh,
                        const __nv_bfloat16* __restrict__ Bl,
                        const float* __restrict__ bias, float* __restrict__ C,
                        int M, int N, int K)
{
    extern __shared__ char sm[];
    const uint32_t sbase = smem_u32(sm);

    const int tid  = threadIdx.x;
    const int lane = tid & 31;
    const int wid  = tid >> 5;
    const int wm   = (wid & 3) * 32;    // 4 warps along M (128)
    const int wn   = (wid >> 2) * 32;   // 2 warps along N (64)
    const int m0   = blockIdx.y * 128;
    const int n0   = blockIdx.x * 64;

    const __nv_bfloat16* abase[2] = { Ah + (size_t)m0 * K, Al + (size_t)m0 * K };
    const __nv_bfloat16* bbase[2] = { Bh + (size_t)n0 * K, Bl + (size_t)n0 * K };

    float d[2][4][4];
#pragma unroll
    for (int i = 0; i < 2; i++)
#pragma unroll
        for (int j = 0; j < 4; j++)
#pragma unroll
            for (int q = 0; q < 4; q++) d[i][j][q] = 0.f;

    auto issue = [&](int c) {
        const int s = c & 1;
        const int k0 = c * 64;
        const uint32_t sb = sbase + s * STAGEB;
        // A tiles: 2 x 1024 chunks -> 8 per thread
#pragma unroll
        for (int i = 0; i < 8; i++) {
            const int tile = i >> 2;
            const int idx  = (i & 3) * 256 + tid;
            const int row  = idx >> 3;              // 0..127
            const int q    = idx & 7;
            const __nv_bfloat16* src = abase[tile] + (size_t)row * K + k0 + q * 8;
            const uint32_t dst = sb + tile * ATILEB + sw128(row * 128 + q * 16);
            CP_ASYNC16(dst, src);
        }
        // B tiles: 2 x 512 chunks -> 4 per thread
#pragma unroll
        for (int i = 0; i < 4; i++) {
            const int tile = i >> 1;
            const int idx  = (i & 1) * 256 + tid;
            const int row  = idx >> 3;              // 0..63
            const int q    = idx & 7;
            const __nv_bfloat16* src = bbase[tile] + (size_t)row * K + k0 + q * 8;
            const uint32_t dst = sb + 2 * ATILEB + tile * BTILEB
                               + sw128(row * 128 + q * 16);
            CP_ASYNC16(dst, src);
        }
        CP_COMMIT();
    };

    auto compute = [&](int s) {
        const uint32_t sb = sbase + s * STAGEB;
#pragma unroll
        for (int ks = 0; ks < 4; ks++) {
            const uint32_t colb = ks * 32 + ((lane >> 4) << 4);

            uint32_t bh[4][2], bl[4][2];
#pragma unroll
            for (int ng = 0; ng < 2; ng++) {
                uint32_t off = sw128((wn + ng * 16 + (lane & 15)) * 128 + colb);
                uint32_t r[4];
                LDSM4(r, sb + 2 * ATILEB + off);
                bh[ng * 2 + 0][0] = r[0]; bh[ng * 2 + 0][1] = r[2];
                bh[ng * 2 + 1][0] = r[1]; bh[ng * 2 + 1][1] = r[3];
                LDSM4(r, sb + 2 * ATILEB + BTILEB + off);
                bl[ng * 2 + 0][0] = r[0]; bl[ng * 2 + 0][1] = r[2];
                bl[ng * 2 + 1][0] = r[1]; bl[ng * 2 + 1][1] = r[3];
            }

#pragma unroll
            for (int mt = 0; mt < 2; mt++) {
                uint32_t off = sw128((wm + mt * 16 + (lane & 15)) * 128 + colb);
                uint32_t ah[4], al[4];
                LDSM4(ah, sb + off);
                LDSM4(al, sb + ATILEB + off);
#pragma unroll
                for (int nt = 0; nt < 4; nt++) {
                    mma16816(d[mt][nt], ah, bh[nt]);
                    mma16816(d[mt][nt], ah, bl[nt]);
                    mma16816(d[mt][nt], al, bh[nt]);
                }
            }
        }
    };

    const int NC = K / 64;
    issue(0);
    for (int c = 0; c < NC; c++) {
        if (c + 1 < NC) {
            issue(c + 1);
            CP_WAIT1();
        } else {
            CP_WAIT0();
        }
        __syncthreads();
        compute(c & 1);
        __syncthreads();
    }

    // epilogue
#pragma unroll
    for (int mt = 0; mt < 2; mt++) {
        const int r0 = m0 + wm + mt * 16 + (lane >> 2);
#pragma unroll
        for (int nt = 0; nt < 4; nt++) {
            const int c0 = n0 + wn + nt * 8 + (lane & 3) * 2;
            const float b0 = bias[c0], b1 = bias[c0 + 1];
            float2 o;
            o.x = d[mt][nt][0] + b0;
            o.y = d[mt][nt][1] + b1;
            *(float2*)(C + (size_t)r0 * N + c0) = o;
            o.x = d[mt][nt][2] + b0;
            o.y = d[mt][nt][3] + b1;
            *(float2*)(C + (size_t)(r0 + 8) * N + c0) = o;
        }
    }
}

// ---------------------------------------------------------------------------
// Banded scores + softmax + attn@V — float4 LDS paths, stride 68, 5 CTAs/SM
// ---------------------------------------------------------------------------
#define TI    8
#define NUMAX 144
#define KVST  68
#define NT    256

__global__ __launch_bounds__(NT)
void scores_attn_kernel(const float* __restrict__ qkv,
                        float* __restrict__ scores_out,
                        __nv_bfloat16* __restrict__ attn_hi,
                        __nv_bfloat16* __restrict__ attn_lo)
{
    __shared__ float KVs[NUMAX * KVST];   // 39168 B
    __shared__ float Qs[TI * KVST];       // 2176 B
    __shared__ float Sc[TI * NUMAX];      // 4608 B  (raw scores, then probs)

    const int h  = blockIdx.y;
    const int i0 = blockIdx.x * TI;
    const int t  = threadIdx.x;

    const int j0 = max(0, i0 - KNB);
    const int j1 = min(S_ - 1, i0 + TI - 1 + KNB);
    const int NU = j1 - j0 + 1;           // <= 136

    const int hoff = h * DH_;

    // load Q tile [TI x 64] float4
    for (int idx = t; idx < TI * 16; idx += NT) {
        int r = idx >> 4, dq = idx & 15;
        *(float4*)(Qs + r * KVST + dq * 4) =
            *(const float4*)(qkv + (size_t)(i0 + r) * E3_ + hoff + dq * 4);
    }
    // load K band [NU x 64] float4
    for (int idx = t; idx < NU * 16; idx += NT) {
        int u = idx >> 4, dq = idx & 15;
        *(float4*)(KVs + u * KVST + dq * 4) =
            *(const float4*)(qkv + (size_t)(j0 + u) * E3_ + E_ + hoff + dq * 4);
    }
    __syncthreads();

    // scores: thread t owns key column u=t; float4 dot over d
    if (t < NU) {
        const int j = j0 + t;
        const float4* kv4 = (const float4*)(KVs + t * KVST);
#pragma unroll
        for (int r = 0; r < TI; r++) {
            const int i = i0 + r;
            float val;
            if (abs(i - j) <= KNB) {
                const float4* q4 = (const float4*)(Qs + r * KVST);
                float s = 0.f;
#pragma unroll
                for (int dq = 0; dq < 16; dq++) {
                    float4 a = q4[dq], b = kv4[dq];
                    s = fmaf(a.x, b.x, s);
                    s = fmaf(a.y, b.y, s);
                    s = fmaf(a.z, b.z, s);
                    s = fmaf(a.w, b.w, s);
                }
                val = s * 0.125f;
            } else {
                val = -INFINITY;
            }
            Sc[r * NUMAX + t] = val;
        }
    }
    __syncthreads();

    // V band load overlaps the large scores stores (K no longer needed)
    for (int idx = t; idx < NU * 16; idx += NT) {
        int u = idx >> 4, dq = idx & 15;
        *(float4*)(KVs + u * KVST + dq * 4) =
            *(const float4*)(qkv + (size_t)(j0 + u) * E3_ + 2 * E_ + hoff + dq * 4);
    }

    // masked scores rows -> gmem (reads Sc)
#pragma unroll
    for (int r = 0; r < TI; r++) {
        const int i = i0 + r;
        const int lo = i - KNB, hi = i + KNB;
        float* rowp = scores_out + ((size_t)h * S_ + i) * S_;
#pragma unroll
        for (int it = 0; it < S_ / (NT * 4); it++) {
            const int j = (it * NT + t) * 4;
            float4 v;
            v.x = (j + 0 >= lo && j + 0 <= hi) ? Sc[r * NUMAX + (j + 0 - j0)] : MASKV;
            v.y = (j + 1 >= lo && j + 1 <= hi) ? Sc[r * NUMAX + (j + 1 - j0)] : MASKV;
            v.z = (j + 2 >= lo && j + 2 <= hi) ? Sc[r * NUMAX + (j + 2 - j0)] : MASKV;
            v.w = (j + 3 >= lo && j + 3 <= hi) ? Sc[r * NUMAX + (j + 3 - j0)] : MASKV;
            *(float4*)(rowp + j) = v;
        }
    }
    __syncthreads();   // Sc reads done before in-place softmax

    // softmax in place (warp w -> row w)
    const int w = t >> 5, lane = t & 31;
    {
        float m = -INFINITY;
        for (int u = lane; u < NU; u += 32)
            m = fmaxf(m, Sc[w * NUMAX + u]);
#pragma unroll
        for (int o = 16; o; o >>= 1)
            m = fmaxf(m, __shfl_xor_sync(0xFFFFFFFFu, m, o));
        float ssum = 0.f;
        for (int u = lane; u < NU; u += 32) {
            float e = expf(Sc[w * NUMAX + u] - m);
            Sc[w * NUMAX + u] = e;
            ssum += e;
        }
#pragma unroll
        for (int o = 16; o; o >>= 1)
            ssum += __shfl_xor_sync(0xFFFFFFFFu, ssum, o);
        float inv = 1.f / ssum;
        for (int u = lane; u < NU; u += 32)
            Sc[w * NUMAX + u] *= inv;
    }
    __syncthreads();

    // attn @ V (float4): threads 0..127, thread owns (row r, 4 d-cols)
    if (t < 128) {
        const int r  = t >> 4;
        const int dg = t & 15;
        const float* pr = Sc + r * NUMAX;
        float4 acc = make_float4(0.f, 0.f, 0.f, 0.f);
        for (int u = 0; u < NU; u++) {
            const float p = pr[u];
            const float4 v = *(const float4*)(KVs + u * KVST + dg * 4);
            acc.x = fmaf(p, v.x, acc.x);
            acc.y = fmaf(p, v.y, acc.y);
            acc.z = fmaf(p, v.z, acc.z);
            acc.w = fmaf(p, v.w, acc.w);
        }
        // bf16 hi/lo split, packed stores
        __nv_bfloat162 h01 = __float22bfloat162_rn(make_float2(acc.x, acc.y));
        __nv_bfloat162 h23 = __float22bfloat162_rn(make_float2(acc.z, acc.w));
        float2 f01 = __bfloat1622float2(h01);
        float2 f23 = __bfloat1622float2(h23);
        __nv_bfloat162 l01 = __float22bfloat162_rn(make_float2(acc.x - f01.x, acc.y - f01.y));
        __nv_bfloat162 l23 = __float22bfloat162_rn(make_float2(acc.z - f23.x, acc.w - f23.y));
        const size_t idx = (size_t)(i0 + r) * E_ + hoff + dg * 4;
        uint2 hv, lv;
        hv.x = *(uint32_t*)&h01; hv.y = *(uint32_t*)&h23;
        lv.x = *(uint32_t*)&l01; lv.y = *(uint32_t*)&l23;
        *(uint2*)(attn_hi + idx) = hv;
        *(uint2*)(attn_lo + idx) = lv;
    }
}

// ---------------------------------------------------------------------------
// launch
// ---------------------------------------------------------------------------
extern "C" void kernel_launch(void* const* d_in, const int* in_sizes, int n_in,
                              void* d_out, int out_size)
{
    const float* x     = (const float*)d_in[0];
    const float* W_qkv = (const float*)d_in[1];
    const float* b_qkv = (const float*)d_in[2];
    const float* W_out = (const float*)d_in[3];
    const float* b_out = (const float*)d_in[4];

    float* out_ptr    = (float*)d_out;
    float* scores_ptr = out_ptr + (size_t)S_ * E_;

    float* qkv_p;
    __nv_bfloat16 *xh, *xl, *wqh, *wql, *woh, *wol, *ah, *al;
    cudaGetSymbolAddress((void**)&qkv_p, g_qkv);
    cudaGetSymbolAddress((void**)&xh,  g_xh);
    cudaGetSymbolAddress((void**)&xl,  g_xl);
    cudaGetSymbolAddress((void**)&wqh, g_wqh);
    cudaGetSymbolAddress((void**)&wql, g_wql);
    cudaGetSymbolAddress((void**)&woh, g_woh);
    cudaGetSymbolAddress((void**)&wol, g_wol);
    cudaGetSymbolAddress((void**)&ah,  g_ah);
    cudaGetSymbolAddress((void**)&al,  g_al);

    cudaFuncSetAttribute(bf16s_gemm_nt_bias,
                         cudaFuncAttributeMaxDynamicSharedMemorySize, GSMEM);

    // splits
    {
        int n4 = (S_ * E_) / 4;
        split_bf16<<<(n4 + 255) / 256, 256>>>((const float4*)x, (uint2*)xh, (uint2*)xl, n4);
    }
    {
        int n4 = (E3_ * E_) / 4;
        split_bf16<<<(n4 + 255) / 256, 256>>>((const float4*)W_qkv, (uint2*)wqh, (uint2*)wql, n4);
    }
    {
        int n4 = (E_ * E_) / 4;
        split_bf16<<<(n4 + 255) / 256, 256>>>((const float4*)W_out, (uint2*)woh, (uint2*)wol, n4);
    }

    // 1) QKV projection
    {
        dim3 grid(E3_ / 64, S_ / 128);
        bf16s_gemm_nt_bias<<<grid, 256, GSMEM>>>(xh, xl, wqh, wql, b_qkv, qkv_p,
                                                 S_, E3_, E_);
    }

    // 2) banded scores + softmax + attn@V
    {
        dim3 grid(S_ / TI, H_);
        scores_attn_kernel<<<grid, NT>>>(qkv_p, scores_ptr, ah, al);
    }

    // 3) output projection
    {
        dim3 grid(E_ / 64, S_ / 128);
        bf16s_gemm_nt_bias<<<grid, 256, GSMEM>>>(ah, al, woh, wol, b_out, out_ptr,
                                                 S_, E_, E_);
    }
}